// round 1
// baseline (speedup 1.0000x reference)
#include <cuda_runtime.h>
#include <math.h>

#define B_  128
#define T_  2048
#define D_  512
#define SPLITS 8            // T splits for msa partials
#define TS (T_ / SPLITS)    // 256

// ---------------- scratch (no allocations allowed) ----------------
__device__ float g_ca[B_ * T_];                 // logits -> normalized weights (in place)
__device__ float g_part[B_ * SPLITS * D_];      // msa partial sums
__device__ float g_m1[B_ * D_];                 // m1 activations

// ---------------- kernel 1: attention logits ----------------
// ca[b,t] = sum_d past_controls[b,t,d] * (control[b,d]*W_ca[d]) + b_ca
// grid (T/64, B), 256 threads; warp handles 8 consecutive t.
__global__ void k_logits(const float* __restrict__ past,
                         const float* __restrict__ control,
                         const float* __restrict__ W_ca,
                         const float* __restrict__ b_ca)
{
    const int b   = blockIdx.y;
    const int tid = threadIdx.x;
    __shared__ float4 s_cw[D_ / 4];     // 128 float4

    if (tid < D_ / 4) {
        float4 c = reinterpret_cast<const float4*>(control + (size_t)b * D_)[tid];
        float4 w = reinterpret_cast<const float4*>(W_ca)[tid];
        s_cw[tid] = make_float4(c.x * w.x, c.y * w.y, c.z * w.z, c.w * w.w);
    }
    __syncthreads();

    const int warp = tid >> 5, lane = tid & 31;
    const float bias = b_ca[0];
    const float* base = past + (size_t)b * T_ * (2 * D_);
    const int t0 = blockIdx.x * 64 + warp * 8;

    #pragma unroll
    for (int i = 0; i < 8; i++) {
        const int t = t0 + i;
        const float4* row = reinterpret_cast<const float4*>(base + (size_t)t * (2 * D_));
        float acc = 0.f;
        #pragma unroll
        for (int j = 0; j < 4; j++) {
            float4 v = row[lane + j * 32];
            float4 c = s_cw[lane + j * 32];
            acc += v.x * c.x + v.y * c.y + v.z * c.z + v.w * c.w;
        }
        #pragma unroll
        for (int o = 16; o; o >>= 1) acc += __shfl_xor_sync(0xffffffffu, acc, o);
        if (lane == 0) g_ca[b * T_ + t] = acc + bias;
    }
}

// ---------------- kernel 2: masked softmax over T (in place) ----------------
// grid (B), 256 threads; 8 values per thread.
__global__ void k_softmax()
{
    const int b = blockIdx.x, tid = threadIdx.x;
    float* row = g_ca + (size_t)b * T_;
    float v[8];
    float mx = -3.4e38f;
    #pragma unroll
    for (int i = 0; i < 8; i++) {
        float x = row[tid + i * 256];
        if (x == 0.f) x = -1e9f;            // mask: exact-zero logits masked out
        v[i] = x;
        mx = fmaxf(mx, x);
    }
    __shared__ float red[256];
    red[tid] = mx; __syncthreads();
    for (int s = 128; s; s >>= 1) { if (tid < s) red[tid] = fmaxf(red[tid], red[tid + s]); __syncthreads(); }
    mx = red[0]; __syncthreads();

    float sum = 0.f;
    #pragma unroll
    for (int i = 0; i < 8; i++) { v[i] = expf(v[i] - mx); sum += v[i]; }
    red[tid] = sum; __syncthreads();
    for (int s = 128; s; s >>= 1) { if (tid < s) red[tid] += red[tid + s]; __syncthreads(); }
    const float inv = 1.f / red[0];
    #pragma unroll
    for (int i = 0; i < 8; i++) row[tid + i * 256] = v[i] * inv;
}

// ---------------- kernel 3: msa partial sums ----------------
// g_part[b,s,:] = sum_{t in split s} w[b,t] * past_memories[b,t,:]
// grid (SPLITS, B), 128 threads; thread owns 4 d's via float4.
__global__ void k_msa(const float* __restrict__ past)
{
    const int b = blockIdx.y, s = blockIdx.x, tid = threadIdx.x;
    const float* base = past + (size_t)b * T_ * (2 * D_) + D_;   // memories half
    const float* wrow = g_ca + (size_t)b * T_ + s * TS;

    __shared__ float s_w[TS];
    s_w[tid]       = wrow[tid];
    s_w[tid + 128] = wrow[tid + 128];
    __syncthreads();

    float4 acc = make_float4(0.f, 0.f, 0.f, 0.f);
    #pragma unroll 8
    for (int t = 0; t < TS; t++) {
        const float wt = s_w[t];
        float4 v = reinterpret_cast<const float4*>(base + (size_t)(s * TS + t) * (2 * D_))[tid];
        acc.x += wt * v.x; acc.y += wt * v.y; acc.z += wt * v.z; acc.w += wt * v.w;
    }
    reinterpret_cast<float4*>(g_part + (size_t)(b * SPLITS + s) * D_)[tid] = acc;
}

// ---------------- kernel 4: m1 = concat(memory, read) @ W_m1 + b_m1 ----------------
// grid (4 n-tiles, 16 batch-groups of 8), 128 threads (one output column each).
__global__ void k_m1(const float* __restrict__ memory,
                     const float* __restrict__ read,
                     const float* __restrict__ W_m1,
                     const float* __restrict__ b_m1)
{
    const int bg  = blockIdx.y;
    const int k   = blockIdx.x * 128 + threadIdx.x;
    const int tid = threadIdx.x;

    __shared__ float s_a[8][2 * D_];   // 32 KB
    for (int i = tid; i < 8 * 2 * D_; i += 128) {
        const int bb = i / (2 * D_), j = i % (2 * D_);
        const int b = bg * 8 + bb;
        s_a[bb][j] = (j < D_) ? memory[b * D_ + j] : read[b * D_ + (j - D_)];
    }
    __syncthreads();

    float acc[8] = {};
    for (int j = 0; j < 2 * D_; j++) {
        const float wv = __ldg(&W_m1[(size_t)j * D_ + k]);
        #pragma unroll
        for (int bb = 0; bb < 8; bb++) acc[bb] += s_a[bb][j] * wv;
    }
    const float bias = b_m1[k];
    #pragma unroll
    for (int bb = 0; bb < 8; bb++)
        g_m1[(size_t)(bg * 8 + bb) * D_ + k] = acc[bb] + bias;
}

// ---------------- kernel 5: final fuse ----------------
// mp = m1@W_m2 + b_m2 + msa@W_s + b_s ; gate = sigmoid(control@W_m3 + b_m3)
// out = mp*gate + (1-gate)*memory
// grid (4 n-tiles, 16 batch-groups of 8), 128 threads.
__global__ void k_final(const float* __restrict__ W_m2, const float* __restrict__ b_m2,
                        const float* __restrict__ W_s,  const float* __restrict__ b_s,
                        const float* __restrict__ control,
                        const float* __restrict__ W_m3, const float* __restrict__ b_m3,
                        const float* __restrict__ memory,
                        float* __restrict__ out)
{
    const int bg  = blockIdx.y;
    const int k   = blockIdx.x * 128 + threadIdx.x;
    const int tid = threadIdx.x;

    __shared__ float s_m1[8][D_];    // 16 KB
    __shared__ float s_msa[8][D_];   // 16 KB
    __shared__ float s_gate[8];

    for (int i = tid; i < 8 * D_; i += 128) {
        const int bb = i / D_, j = i % D_;
        const int b = bg * 8 + bb;
        s_m1[bb][j] = g_m1[(size_t)b * D_ + j];
        float a = 0.f;
        #pragma unroll
        for (int sp = 0; sp < SPLITS; sp++)
            a += g_part[(size_t)(b * SPLITS + sp) * D_ + j];
        s_msa[bb][j] = a;
    }

    // gates: 4 warps, each handles 2 batches
    const int warp = tid >> 5, lane = tid & 31;
    #pragma unroll
    for (int q = 0; q < 2; q++) {
        const int bb = warp + q * 4;
        const int b  = bg * 8 + bb;
        float a = 0.f;
        for (int j = lane; j < D_; j += 32)
            a += control[b * D_ + j] * W_m3[j];
        #pragma unroll
        for (int o = 16; o; o >>= 1) a += __shfl_xor_sync(0xffffffffu, a, o);
        if (lane == 0) s_gate[bb] = 1.f / (1.f + expf(-(a + b_m3[0])));
    }
    __syncthreads();

    float acc[8] = {};
    for (int j = 0; j < D_; j++) {
        const float w2 = __ldg(&W_m2[(size_t)j * D_ + k]);
        const float ws = __ldg(&W_s [(size_t)j * D_ + k]);
        #pragma unroll
        for (int bb = 0; bb < 8; bb++)
            acc[bb] += s_m1[bb][j] * w2 + s_msa[bb][j] * ws;
    }

    const float bias = b_m2[k] + b_s[k];
    #pragma unroll
    for (int bb = 0; bb < 8; bb++) {
        const int b = bg * 8 + bb;
        const float g = s_gate[bb];
        out[(size_t)b * D_ + k] = (acc[bb] + bias) * g + (1.f - g) * memory[b * D_ + k];
    }
}

// ---------------- launch ----------------
extern "C" void kernel_launch(void* const* d_in, const int* in_sizes, int n_in,
                              void* d_out, int out_size)
{
    const float* memory  = (const float*)d_in[0];
    const float* read    = (const float*)d_in[1];
    const float* control = (const float*)d_in[2];
    const float* past    = (const float*)d_in[3];
    const float* W_m1    = (const float*)d_in[4];
    const float* b_m1    = (const float*)d_in[5];
    const float* W_ca    = (const float*)d_in[6];
    const float* b_ca    = (const float*)d_in[7];
    const float* W_m2    = (const float*)d_in[8];
    const float* b_m2    = (const float*)d_in[9];
    const float* W_s     = (const float*)d_in[10];
    const float* b_s     = (const float*)d_in[11];
    const float* W_m3    = (const float*)d_in[12];
    const float* b_m3    = (const float*)d_in[13];
    float* out = (float*)d_out;

    k_logits<<<dim3(T_ / 64, B_), 256>>>(past, control, W_ca, b_ca);
    k_softmax<<<B_, 256>>>();
    k_msa<<<dim3(SPLITS, B_), 128>>>(past);
    k_m1<<<dim3(4, 16), 128>>>(memory, read, W_m1, b_m1);
    k_final<<<dim3(4, 16), 128>>>(W_m2, b_m2, W_s, b_s, control, W_m3, b_m3, memory, out);
}

// round 2
// speedup vs baseline: 2.2824x; 2.2824x over previous
#include <cuda_runtime.h>
#include <math.h>

#define B_  128
#define T_  2048
#define D_  512
#define MSA_SPLITS 16
#define MSA_TS (T_ / MSA_SPLITS)     // 128
#define M1_KS 8                      // split-K for m1 GEMM (K=1024)
#define F_KS  4                      // split-K for final GEMM (K=512)

// ---------------- scratch (no allocations allowed) ----------------
__device__ float g_ca[B_ * T_];                       // logits -> normalized weights (1 MB)
__device__ float g_part[B_ * MSA_SPLITS * D_];        // msa partial sums (4 MB)
__device__ float g_m1p[M1_KS][B_ * D_];               // m1 split-K partials (2 MB)
__device__ float g_fp[F_KS][B_ * D_];                 // final GEMM partials (1 MB)

// ---------------- kernel 1: attention logits ----------------
// ca[b,t] = <past_controls[b,t,:], control[b,:]*W_ca> + b_ca
// grid (T/64, B), 256 threads; warp handles 8 rows with interleaved loads (MLP=8).
__global__ void k_logits(const float* __restrict__ past,
                         const float* __restrict__ control,
                         const float* __restrict__ W_ca,
                         const float* __restrict__ b_ca)
{
    const int b   = blockIdx.y;
    const int tid = threadIdx.x;
    __shared__ float4 s_cw[D_ / 4];

    if (tid < D_ / 4) {
        float4 c = reinterpret_cast<const float4*>(control + (size_t)b * D_)[tid];
        float4 w = reinterpret_cast<const float4*>(W_ca)[tid];
        s_cw[tid] = make_float4(c.x * w.x, c.y * w.y, c.z * w.z, c.w * w.w);
    }
    __syncthreads();

    const int warp = tid >> 5, lane = tid & 31;
    const float bias = b_ca[0];
    const float* base = past + (size_t)b * T_ * (2 * D_);
    const int t0 = blockIdx.x * 64 + warp * 8;

    float acc[8] = {};
    #pragma unroll
    for (int j = 0; j < 4; j++) {
        const float4 c = s_cw[lane + j * 32];
        #pragma unroll
        for (int i = 0; i < 8; i++) {
            float4 v = reinterpret_cast<const float4*>(
                           base + (size_t)(t0 + i) * (2 * D_))[lane + j * 32];
            acc[i] += v.x * c.x + v.y * c.y + v.z * c.z + v.w * c.w;
        }
    }
    #pragma unroll
    for (int i = 0; i < 8; i++) {
        float a = acc[i];
        #pragma unroll
        for (int o = 16; o; o >>= 1) a += __shfl_xor_sync(0xffffffffu, a, o);
        if (lane == 0) g_ca[b * T_ + t0 + i] = a + bias;
    }
}

// ---------------- kernel 2: masked softmax over T (in place) ----------------
__global__ void k_softmax()
{
    const int b = blockIdx.x, tid = threadIdx.x;
    float* row = g_ca + (size_t)b * T_;
    float v[8];
    float mx = -3.4e38f;
    #pragma unroll
    for (int i = 0; i < 8; i++) {
        float x = row[tid + i * 256];
        if (x == 0.f) x = -1e9f;
        v[i] = x;
        mx = fmaxf(mx, x);
    }
    __shared__ float red[256];
    red[tid] = mx; __syncthreads();
    for (int s = 128; s; s >>= 1) { if (tid < s) red[tid] = fmaxf(red[tid], red[tid + s]); __syncthreads(); }
    mx = red[0]; __syncthreads();

    float sum = 0.f;
    #pragma unroll
    for (int i = 0; i < 8; i++) { v[i] = expf(v[i] - mx); sum += v[i]; }
    red[tid] = sum; __syncthreads();
    for (int s = 128; s; s >>= 1) { if (tid < s) red[tid] += red[tid + s]; __syncthreads(); }
    const float inv = 1.f / red[0];
    #pragma unroll
    for (int i = 0; i < 8; i++) row[tid + i * 256] = v[i] * inv;
}

// ---------------- kernel 3: msa partial sums ----------------
// g_part[b,s,:] = sum_{t in split s} w[b,t] * past_memories[b,t,:]
// grid (MSA_SPLITS, B), 128 threads; 4 independent float4 accumulators (ILP=4).
__global__ void k_msa(const float* __restrict__ past)
{
    const int b = blockIdx.y, s = blockIdx.x, tid = threadIdx.x;
    const float* base = past + (size_t)b * T_ * (2 * D_) + D_ + (size_t)s * MSA_TS * (2 * D_);
    const float* wrow = g_ca + (size_t)b * T_ + s * MSA_TS;

    __shared__ float s_w[MSA_TS];
    s_w[tid] = wrow[tid];
    __syncthreads();

    float4 a0 = {0,0,0,0}, a1 = {0,0,0,0}, a2 = {0,0,0,0}, a3 = {0,0,0,0};
    #pragma unroll 4
    for (int t = 0; t < MSA_TS; t += 4) {
        float4 v0 = reinterpret_cast<const float4*>(base + (size_t)(t + 0) * (2 * D_))[tid];
        float4 v1 = reinterpret_cast<const float4*>(base + (size_t)(t + 1) * (2 * D_))[tid];
        float4 v2 = reinterpret_cast<const float4*>(base + (size_t)(t + 2) * (2 * D_))[tid];
        float4 v3 = reinterpret_cast<const float4*>(base + (size_t)(t + 3) * (2 * D_))[tid];
        const float w0 = s_w[t], w1 = s_w[t + 1], w2 = s_w[t + 2], w3 = s_w[t + 3];
        a0.x += w0 * v0.x; a0.y += w0 * v0.y; a0.z += w0 * v0.z; a0.w += w0 * v0.w;
        a1.x += w1 * v1.x; a1.y += w1 * v1.y; a1.z += w1 * v1.z; a1.w += w1 * v1.w;
        a2.x += w2 * v2.x; a2.y += w2 * v2.y; a2.z += w2 * v2.z; a2.w += w2 * v2.w;
        a3.x += w3 * v3.x; a3.y += w3 * v3.y; a3.z += w3 * v3.z; a3.w += w3 * v3.w;
    }
    float4 acc = make_float4((a0.x + a1.x) + (a2.x + a3.x),
                             (a0.y + a1.y) + (a2.y + a3.y),
                             (a0.z + a1.z) + (a2.z + a3.z),
                             (a0.w + a1.w) + (a2.w + a3.w));
    reinterpret_cast<float4*>(g_part + (size_t)(b * MSA_SPLITS + s) * D_)[tid] = acc;
}

// ---------------- kernel 4: m1 GEMM, split-K ----------------
// grid (4 n-tiles, 16 batch-groups of 8, M1_KS k-slices), 128 threads.
__global__ void k_m1(const float* __restrict__ memory,
                     const float* __restrict__ read,
                     const float* __restrict__ W_m1)
{
    const int bg = blockIdx.y, ks = blockIdx.z;
    const int k  = blockIdx.x * 128 + threadIdx.x;
    const int tid = threadIdx.x;

    __shared__ float s_a[8][128];
    for (int i = tid; i < 8 * 128; i += 128) {
        const int bb = i >> 7, j = i & 127;
        const int jj = ks * 128 + j;
        const int b = bg * 8 + bb;
        s_a[bb][j] = (jj < D_) ? memory[b * D_ + jj] : read[b * D_ + (jj - D_)];
    }
    __syncthreads();

    float acc[8] = {};
    const float* Wb = W_m1 + (size_t)(ks * 128) * D_ + k;
    #pragma unroll 4
    for (int j = 0; j < 128; j++) {
        const float wv = __ldg(&Wb[(size_t)j * D_]);
        #pragma unroll
        for (int bb = 0; bb < 8; bb++) acc[bb] += s_a[bb][j] * wv;
    }
    #pragma unroll
    for (int bb = 0; bb < 8; bb++)
        g_m1p[ks][(size_t)(bg * 8 + bb) * D_ + k] = acc[bb];
}

// ---------------- kernel 5: final GEMM (m1@W_m2 + msa@W_s), split-K ----------------
// grid (4 n-tiles, 16 batch-groups, F_KS k-slices), 128 threads.
__global__ void k_fgemm(const float* __restrict__ W_m2,
                        const float* __restrict__ W_s,
                        const float* __restrict__ b_m1)
{
    const int bg = blockIdx.y, ks = blockIdx.z;
    const int k  = blockIdx.x * 128 + threadIdx.x;
    const int tid = threadIdx.x;

    __shared__ float s_m1[8][128];
    __shared__ float s_msa[8][128];
    for (int i = tid; i < 8 * 128; i += 128) {
        const int bb = i >> 7, j = i & 127;
        const int jj = ks * 128 + j;
        const int b = bg * 8 + bb;
        float m1 = b_m1[jj];
        #pragma unroll
        for (int p = 0; p < M1_KS; p++) m1 += g_m1p[p][(size_t)b * D_ + jj];
        float ms = 0.f;
        #pragma unroll
        for (int sp = 0; sp < MSA_SPLITS; sp++)
            ms += g_part[(size_t)(b * MSA_SPLITS + sp) * D_ + jj];
        s_m1[bb][j] = m1;
        s_msa[bb][j] = ms;
    }
    __syncthreads();

    float acc[8] = {};
    const float* W2b = W_m2 + (size_t)(ks * 128) * D_ + k;
    const float* Wsb = W_s  + (size_t)(ks * 128) * D_ + k;
    #pragma unroll 4
    for (int j = 0; j < 128; j++) {
        const float w2 = __ldg(&W2b[(size_t)j * D_]);
        const float ws = __ldg(&Wsb[(size_t)j * D_]);
        #pragma unroll
        for (int bb = 0; bb < 8; bb++)
            acc[bb] += s_m1[bb][j] * w2 + s_msa[bb][j] * ws;
    }
    #pragma unroll
    for (int bb = 0; bb < 8; bb++)
        g_fp[ks][(size_t)(bg * 8 + bb) * D_ + k] = acc[bb];
}

// ---------------- kernel 6: epilogue (gate + bias + blend) ----------------
// grid (B), 512 threads; one block per batch, one thread per output column.
__global__ void k_epi(const float* __restrict__ control,
                      const float* __restrict__ W_m3, const float* __restrict__ b_m3,
                      const float* __restrict__ b_m2, const float* __restrict__ b_s,
                      const float* __restrict__ memory,
                      float* __restrict__ out)
{
    const int b = blockIdx.x, tid = threadIdx.x;

    __shared__ float red[512];
    red[tid] = control[(size_t)b * D_ + tid] * W_m3[tid];
    __syncthreads();
    for (int s = 256; s; s >>= 1) { if (tid < s) red[tid] += red[tid + s]; __syncthreads(); }
    __shared__ float s_gate;
    if (tid == 0) s_gate = 1.f / (1.f + expf(-(red[0] + b_m3[0])));
    __syncthreads();

    float acc = b_m2[tid] + b_s[tid];
    #pragma unroll
    for (int p = 0; p < F_KS; p++) acc += g_fp[p][(size_t)b * D_ + tid];

    const float g = s_gate;
    out[(size_t)b * D_ + tid] = acc * g + (1.f - g) * memory[(size_t)b * D_ + tid];
}

// ---------------- launch ----------------
extern "C" void kernel_launch(void* const* d_in, const int* in_sizes, int n_in,
                              void* d_out, int out_size)
{
    const float* memory  = (const float*)d_in[0];
    const float* read    = (const float*)d_in[1];
    const float* control = (const float*)d_in[2];
    const float* past    = (const float*)d_in[3];
    const float* W_m1    = (const float*)d_in[4];
    const float* b_m1    = (const float*)d_in[5];
    const float* W_ca    = (const float*)d_in[6];
    const float* b_ca    = (const float*)d_in[7];
    const float* W_m2    = (const float*)d_in[8];
    const float* b_m2    = (const float*)d_in[9];
    const float* W_s     = (const float*)d_in[10];
    const float* b_s     = (const float*)d_in[11];
    const float* W_m3    = (const float*)d_in[12];
    const float* b_m3    = (const float*)d_in[13];
    float* out = (float*)d_out;

    k_logits<<<dim3(T_ / 64, B_), 256>>>(past, control, W_ca, b_ca);
    k_softmax<<<B_, 256>>>();
    k_msa<<<dim3(MSA_SPLITS, B_), 128>>>(past);
    k_m1<<<dim3(4, 16, M1_KS), 128>>>(memory, read, W_m1);
    k_fgemm<<<dim3(4, 16, F_KS), 128>>>(W_m2, W_s, b_m1);
    k_epi<<<B_, 512>>>(control, W_m3, b_m3, b_m2, b_s, memory, out);
}

// round 3
// speedup vs baseline: 2.7009x; 1.1834x over previous
#include <cuda_runtime.h>
#include <math.h>

#define B_  128
#define T_  2048
#define D_  512
#define MSA_SPLITS 16
#define MSA_TS (T_ / MSA_SPLITS)     // 128
#define M1_KS 8                      // split-K for m1 GEMM (K=1024)
#define F2_KS 4                      // split-K for m1@W_m2 (K=512)
#define FS_KS 8                      // split-K for msa@W_s (K=512, 64-wide slices)

// ---------------- scratch (no allocations allowed) ----------------
__device__ float  g_ca[B_ * T_];                    // raw logits (1 MB)
__device__ float2 g_norm[B_];                       // {max, 1/sum}
__device__ float  g_part[B_ * MSA_SPLITS * D_];     // msa partials (4 MB)
__device__ float  g_m1p[M1_KS][B_ * D_];            // m1 split-K partials (2 MB)
__device__ float  g_f2p[F2_KS][B_ * D_];            // m1@W_m2 partials (1 MB)
__device__ float  g_fsp[FS_KS][B_ * D_];            // msa@W_s partials (2 MB)
__device__ float  g_gate[B_];                       // sigmoid gates

// ================= K1: m1 GEMM blocks + logits stream + gate block =================
// blocks [0,256): m1 split-K GEMM; [256, 256+4096): logits; [4352]: gate.
__global__ __launch_bounds__(256) void k1(const float* __restrict__ past,
                                          const float* __restrict__ control,
                                          const float* __restrict__ W_ca,
                                          const float* __restrict__ b_ca,
                                          const float* __restrict__ memory,
                                          const float* __restrict__ read,
                                          const float* __restrict__ W_m1,
                                          const float* __restrict__ W_m3,
                                          const float* __restrict__ b_m3)
{
    __shared__ float sbuf[8 * 128];           // 4 KB, reused per role
    const int tid = threadIdx.x;
    int bid = blockIdx.x;

    if (bid < 256) {
        // ---- m1 GEMM: g_m1p[ks][b, k] = sum_{j in slice ks} A[b,jj] * W_m1[jj,k]
        const int ks = bid & 7, bg = (bid >> 3) & 15, st = bid >> 7;
        const int k = st * 256 + tid;
        float (*s_a)[128] = reinterpret_cast<float (*)[128]>(sbuf);
        for (int i = tid; i < 8 * 128; i += 256) {
            const int bb = i >> 7, j = i & 127;
            const int jj = ks * 128 + j;
            const int b = bg * 8 + bb;
            s_a[bb][j] = (jj < D_) ? memory[b * D_ + jj] : read[b * D_ + (jj - D_)];
        }
        __syncthreads();
        float acc[8] = {};
        const float* Wb = W_m1 + (size_t)(ks * 128) * D_ + k;
        #pragma unroll 4
        for (int j = 0; j < 128; j++) {
            const float wv = __ldg(&Wb[(size_t)j * D_]);
            #pragma unroll
            for (int bb = 0; bb < 8; bb++) acc[bb] += s_a[bb][j] * wv;
        }
        #pragma unroll
        for (int bb = 0; bb < 8; bb++)
            g_m1p[ks][(size_t)(bg * 8 + bb) * D_ + k] = acc[bb];
        return;
    }
    if (bid == 4352) {
        // ---- gate: g_gate[b] = sigmoid(control[b,:]·W_m3 + b_m3)
        const int warp = tid >> 5, lane = tid & 31;
        #pragma unroll
        for (int q = 0; q < 16; q++) {
            const int b = warp * 16 + q;
            float a = 0.f;
            #pragma unroll
            for (int j = 0; j < 16; j++)
                a += control[(size_t)b * D_ + lane + j * 32] * W_m3[lane + j * 32];
            #pragma unroll
            for (int o = 16; o; o >>= 1) a += __shfl_xor_sync(0xffffffffu, a, o);
            if (lane == 0) g_gate[b] = 1.f / (1.f + expf(-(a + b_m3[0])));
        }
        return;
    }

    // ---- logits: ca[b,t] = <past_controls[b,t,:], control[b,:]*W_ca> + b_ca
    bid -= 256;
    const int b = bid >> 5, tile = bid & 31;
    float4* s_cw = reinterpret_cast<float4*>(sbuf);
    if (tid < D_ / 4) {
        float4 c = reinterpret_cast<const float4*>(control + (size_t)b * D_)[tid];
        float4 w = reinterpret_cast<const float4*>(W_ca)[tid];
        s_cw[tid] = make_float4(c.x * w.x, c.y * w.y, c.z * w.z, c.w * w.w);
    }
    __syncthreads();

    const int warp = tid >> 5, lane = tid & 31;
    const float bias = b_ca[0];
    const float* base = past + (size_t)b * T_ * (2 * D_);
    const int t0 = tile * 64 + warp * 8;

    float acc[8] = {};
    #pragma unroll
    for (int j = 0; j < 4; j++) {
        const float4 c = s_cw[lane + j * 32];
        #pragma unroll
        for (int i = 0; i < 8; i++) {
            float4 v = reinterpret_cast<const float4*>(
                           base + (size_t)(t0 + i) * (2 * D_))[lane + j * 32];
            acc[i] += v.x * c.x + v.y * c.y + v.z * c.z + v.w * c.w;
        }
    }
    #pragma unroll
    for (int i = 0; i < 8; i++) {
        float a = acc[i];
        #pragma unroll
        for (int o = 16; o; o >>= 1) a += __shfl_xor_sync(0xffffffffu, a, o);
        if (lane == 0) g_ca[b * T_ + t0 + i] = a + bias;
    }
}

// ================= K2: softmax stats (max + 1/sum per batch) =================
__global__ __launch_bounds__(256) void k2()
{
    const int b = blockIdx.x, tid = threadIdx.x;
    const float* row = g_ca + (size_t)b * T_;
    float v[8];
    float mx = -3.4e38f;
    #pragma unroll
    for (int i = 0; i < 8; i++) {
        float x = row[tid + i * 256];
        if (x == 0.f) x = -1e9f;
        v[i] = x;
        mx = fmaxf(mx, x);
    }
    __shared__ float red[256];
    red[tid] = mx; __syncthreads();
    for (int s = 128; s; s >>= 1) { if (tid < s) red[tid] = fmaxf(red[tid], red[tid + s]); __syncthreads(); }
    mx = red[0]; __syncthreads();

    float sum = 0.f;
    #pragma unroll
    for (int i = 0; i < 8; i++) sum += expf(v[i] - mx);
    red[tid] = sum; __syncthreads();
    for (int s = 128; s; s >>= 1) { if (tid < s) red[tid] += red[tid + s]; __syncthreads(); }
    if (tid == 0) g_norm[b] = make_float2(mx, 1.f / red[0]);
}

// ================= K3: m1@W_m2 GEMM blocks + msa stream =================
// blocks [0,128): W_m2 GEMM; [128, 128+2048): msa.
__global__ __launch_bounds__(256) void k3(const float* __restrict__ past,
                                          const float* __restrict__ W_m2,
                                          const float* __restrict__ b_m1)
{
    __shared__ float sbuf[8 * 128];           // 4 KB, reused per role
    const int tid = threadIdx.x;
    int bid = blockIdx.x;

    if (bid < 128) {
        // ---- g_f2p[ks][b,k] = sum_{j in slice} m1[b,jj] * W_m2[jj,k]
        const int ks = bid & 3, bg = (bid >> 2) & 15, st = bid >> 6;
        const int k = st * 256 + tid;
        float (*s_m1)[128] = reinterpret_cast<float (*)[128]>(sbuf);
        for (int i = tid; i < 8 * 128; i += 256) {
            const int bb = i >> 7, j = i & 127;
            const int jj = ks * 128 + j;
            const int b = bg * 8 + bb;
            float m1 = b_m1[jj];
            #pragma unroll
            for (int p = 0; p < M1_KS; p++) m1 += g_m1p[p][(size_t)b * D_ + jj];
            s_m1[bb][j] = m1;
        }
        __syncthreads();
        float acc[8] = {};
        const float* Wb = W_m2 + (size_t)(ks * 128) * D_ + k;
        #pragma unroll 4
        for (int j = 0; j < 128; j++) {
            const float wv = __ldg(&Wb[(size_t)j * D_]);
            #pragma unroll
            for (int bb = 0; bb < 8; bb++) acc[bb] += s_m1[bb][j] * wv;
        }
        #pragma unroll
        for (int bb = 0; bb < 8; bb++)
            g_f2p[ks][(size_t)(bg * 8 + bb) * D_ + k] = acc[bb];
        return;
    }

    // ---- msa: g_part[b,s,:] = sum_{t in split} softmax_w[b,t] * past_memories[b,t,:]
    bid -= 128;
    const int b = bid >> 4, s = bid & 15;
    const float* base = past + (size_t)b * T_ * (2 * D_) + D_ + (size_t)s * MSA_TS * (2 * D_);
    const float2 nrm = g_norm[b];

    float* s_w = sbuf;                  // 128 floats
    if (tid < MSA_TS) {
        float x = g_ca[(size_t)b * T_ + s * MSA_TS + tid];
        if (x == 0.f) x = -1e9f;
        s_w[tid] = expf(x - nrm.x) * nrm.y;
    }
    __syncthreads();

    // 256 threads: thread owns 2 floats (tid in [0,256) -> float2 over D=512)
    const float2* base2 = reinterpret_cast<const float2*>(base);
    float2 a0 = {0,0}, a1 = {0,0}, a2 = {0,0}, a3 = {0,0};
    #pragma unroll 4
    for (int t = 0; t < MSA_TS; t += 4) {
        float2 v0 = base2[(size_t)(t + 0) * D_ + tid];
        float2 v1 = base2[(size_t)(t + 1) * D_ + tid];
        float2 v2 = base2[(size_t)(t + 2) * D_ + tid];
        float2 v3 = base2[(size_t)(t + 3) * D_ + tid];
        const float w0 = s_w[t], w1 = s_w[t + 1], w2 = s_w[t + 2], w3 = s_w[t + 3];
        a0.x += w0 * v0.x; a0.y += w0 * v0.y;
        a1.x += w1 * v1.x; a1.y += w1 * v1.y;
        a2.x += w2 * v2.x; a2.y += w2 * v2.y;
        a3.x += w3 * v3.x; a3.y += w3 * v3.y;
    }
    float2 acc = make_float2((a0.x + a1.x) + (a2.x + a3.x),
                             (a0.y + a1.y) + (a2.y + a3.y));
    reinterpret_cast<float2*>(g_part + (size_t)(b * MSA_SPLITS + s) * D_)[tid] = acc;
}

// ================= K4: msa@W_s GEMM (split-K 8, 64-wide slices) =================
__global__ __launch_bounds__(256) void k4(const float* __restrict__ W_s)
{
    const int bid = blockIdx.x, tid = threadIdx.x;
    const int ks = bid & 7, bg = (bid >> 3) & 15, st = bid >> 7;
    const int k = st * 256 + tid;

    __shared__ float s_msa[8][64];
    for (int i = tid; i < 8 * 64; i += 256) {
        const int bb = i >> 6, j = i & 63;
        const int jj = ks * 64 + j;
        const int b = bg * 8 + bb;
        float ms = 0.f;
        #pragma unroll
        for (int sp = 0; sp < MSA_SPLITS; sp++)
            ms += g_part[(size_t)(b * MSA_SPLITS + sp) * D_ + jj];
        s_msa[bb][j] = ms;
    }
    __syncthreads();

    float acc[8] = {};
    const float* Wb = W_s + (size_t)(ks * 64) * D_ + k;
    #pragma unroll 4
    for (int j = 0; j < 64; j++) {
        const float wv = __ldg(&Wb[(size_t)j * D_]);
        #pragma unroll
        for (int bb = 0; bb < 8; bb++) acc[bb] += s_msa[bb][j] * wv;
    }
    #pragma unroll
    for (int bb = 0; bb < 8; bb++)
        g_fsp[ks][(size_t)(bg * 8 + bb) * D_ + k] = acc[bb];
}

// ================= K5: epilogue =================
__global__ __launch_bounds__(512) void k5(const float* __restrict__ b_m2,
                                          const float* __restrict__ b_s,
                                          const float* __restrict__ memory,
                                          float* __restrict__ out)
{
    const int b = blockIdx.x, k = threadIdx.x;
    float acc = b_m2[k] + b_s[k];
    #pragma unroll
    for (int p = 0; p < F2_KS; p++) acc += g_f2p[p][(size_t)b * D_ + k];
    #pragma unroll
    for (int p = 0; p < FS_KS; p++) acc += g_fsp[p][(size_t)b * D_ + k];
    const float g = g_gate[b];
    out[(size_t)b * D_ + k] = acc * g + (1.f - g) * memory[(size_t)b * D_ + k];
}

// ---------------- launch ----------------
extern "C" void kernel_launch(void* const* d_in, const int* in_sizes, int n_in,
                              void* d_out, int out_size)
{
    const float* memory  = (const float*)d_in[0];
    const float* read    = (const float*)d_in[1];
    const float* control = (const float*)d_in[2];
    const float* past    = (const float*)d_in[3];
    const float* W_m1    = (const float*)d_in[4];
    const float* b_m1    = (const float*)d_in[5];
    const float* W_ca    = (const float*)d_in[6];
    const float* b_ca    = (const float*)d_in[7];
    const float* W_m2    = (const float*)d_in[8];
    const float* b_m2    = (const float*)d_in[9];
    const float* W_s     = (const float*)d_in[10];
    const float* b_s     = (const float*)d_in[11];
    const float* W_m3    = (const float*)d_in[12];
    const float* b_m3    = (const float*)d_in[13];
    float* out = (float*)d_out;

    k1<<<256 + 4096 + 1, 256>>>(past, control, W_ca, b_ca,
                                memory, read, W_m1, W_m3, b_m3);
    k2<<<B_, 256>>>();
    k3<<<128 + 2048, 256>>>(past, W_m2, b_m1);
    k4<<<256, 256>>>(W_s);
    k5<<<B_, 512>>>(b_m2, b_s, memory, out);
}